// round 3
// baseline (speedup 1.0000x reference)
#include <cuda_runtime.h>

#define H  2048
#define S  8192
#define NB 148
#define NT 1024

// Scratch (no allocs allowed). g_u starts zero (static init); block 0 re-zeros
// it at the end of every invocation, so "g_u == 0 on entry" holds for the
// correctness run, the capture, and every graph replay.
__device__ float    g_u[H];
__device__ float    g_mb[NB];
__device__ float    g_zb[NB];
__device__ unsigned g_count = 0;   // barrier arrival counter (self-resetting)
__device__ unsigned g_gen   = 0;   // barrier generation (monotonic across replays)

// Software grid barrier. Safe because all NB blocks are resident
// (NB=148 blocks of 1024 threads on 152 SMs -> wave 1). Sense-reversing via a
// monotonic generation counter: last arriver resets count, fences, bumps gen;
// waiters snapshot gen BEFORE arriving and spin until it changes.
__device__ __forceinline__ void grid_barrier() {
    __syncthreads();
    __threadfence();                       // order this thread's prior stores
    if (threadIdx.x == 0) {
        unsigned gen0 = *(volatile unsigned*)&g_gen;
        if (atomicAdd(&g_count, 1u) == NB - 1) {
            g_count = 0;
            __threadfence();
            atomicAdd(&g_gen, 1u);         // release
        } else {
            while (*(volatile unsigned*)&g_gen == gen0) { }
        }
        __threadfence();                   // acquire
    }
    __syncthreads();
}

__global__ __launch_bounds__(NT, 1)
void fused_attn(const float* __restrict__ hidden,
                const float* __restrict__ enc,
                const float* __restrict__ W,
                float* __restrict__ out) {
    const int b    = blockIdx.x;
    const int tid  = threadIdx.x;
    const int lane = tid & 31;
    const int wid  = tid >> 5;

    __shared__ float sE[56];       // energies of this block's rows
    __shared__ float sM, sInvZ;

    // ---------------- Phase 1: u[j] = sum_i h[i] * W[i,j] ----------------
    // Block b handles i-strip [b*H/NB, (b+1)*H/NB). Threads cover j and j+1024
    // (fully coalesced). Partials atomicAdd'ed into pre-zeroed g_u.
    {
        const int i0 = (b * H) / NB;
        const int i1 = ((b + 1) * H) / NB;
        float a0 = 0.0f, a1 = 0.0f;
        for (int i = i0; i < i1; ++i) {
            const float hv = __ldg(hidden + i);
            a0 = fmaf(hv, W[(size_t)i * H + tid],      a0);
            a1 = fmaf(hv, W[(size_t)i * H + tid + NT], a1);
        }
        atomicAdd(&g_u[tid],      a0);
        atomicAdd(&g_u[tid + NT], a1);
    }

    grid_barrier();   // g_u complete

    // ---------------- Phase 2: energies + block-local (m, z) -------------
    // Block b handles rows s = b + k*NB (k = 0..nrows-1, nrows = 55 or 56).
    // One warp per row; u (8KB) stays L1/L2 resident.
    const int nrows = (S - 1 - b) / NB + 1;

    for (int k = wid; k < nrows; k += 32) {
        const int s = b + k * NB;
        const float4* row = reinterpret_cast<const float4*>(enc + (size_t)s * H);
        const float4* uv  = reinterpret_cast<const float4*>(g_u);
        float acc = 0.0f;
#pragma unroll
        for (int t = 0; t < (H / 4) / 32; ++t) {   // 16 iterations
            float4 v = row[lane + t * 32];
            float4 u = uv [lane + t * 32];
            acc = fmaf(v.x, u.x, acc);
            acc = fmaf(v.y, u.y, acc);
            acc = fmaf(v.z, u.z, acc);
            acc = fmaf(v.w, u.w, acc);
        }
#pragma unroll
        for (int off = 16; off; off >>= 1)
            acc += __shfl_xor_sync(0xFFFFFFFFu, acc, off);
        if (lane == 0) sE[k] = acc;
    }
    __syncthreads();

    if (wid == 0) {
        const float v0 = (lane      < nrows) ? sE[lane]      : -1e30f;
        const float v1 = (lane + 32 < nrows) ? sE[lane + 32] : -1e30f;
        float m = fmaxf(v0, v1);
#pragma unroll
        for (int off = 16; off; off >>= 1)
            m = fmaxf(m, __shfl_xor_sync(0xFFFFFFFFu, m, off));
        float z = 0.0f;
        if (lane      < nrows) z += __expf(v0 - m);
        if (lane + 32 < nrows) z += __expf(v1 - m);
#pragma unroll
        for (int off = 16; off; off >>= 1)
            z += __shfl_xor_sync(0xFFFFFFFFu, z, off);
        if (lane == 0) { g_mb[b] = m; g_zb[b] = z; }
    }

    grid_barrier();   // all (m_b, z_b) visible

    // ---------------- Phase 3: global (M, 1/Z), redundant per block ------
    if (wid == 0) {
        float m = -1e30f;
        for (int i = lane; i < NB; i += 32) m = fmaxf(m, g_mb[i]);
#pragma unroll
        for (int off = 16; off; off >>= 1)
            m = fmaxf(m, __shfl_xor_sync(0xFFFFFFFFu, m, off));
        float z = 0.0f;
        for (int i = lane; i < NB; i += 32) z += g_zb[i] * __expf(g_mb[i] - m);
#pragma unroll
        for (int off = 16; off; off >>= 1)
            z += __shfl_xor_sync(0xFFFFFFFFu, z, off);
        if (lane == 0) { sM = m; sInvZ = 1.0f / z; }
    }
    __syncthreads();

    // ---------------- Phase 4: write softmax, restore g_u invariant ------
    if (tid < nrows)
        out[b + tid * NB] = __expf(sE[tid] - sM) * sInvZ;

    if (b == 0) {                      // all phase-2 readers passed barrier 2
        g_u[tid]      = 0.0f;
        g_u[tid + NT] = 0.0f;
    }
}

// ---------------------------------------------------------------------------
// Launch. Inputs: hidden[2048], encoder_outputs[8192*2048], W[2048*2048],
// b[2048] (zero + softmax-invariant -> ignored). Output: 8192 floats.
// ---------------------------------------------------------------------------
extern "C" void kernel_launch(void* const* d_in, const int* in_sizes, int n_in,
                              void* d_out, int out_size) {
    const float* hidden = (const float*)d_in[0];
    const float* enc    = (const float*)d_in[1];
    const float* W      = (const float*)d_in[2];
    float* out          = (float*)d_out;

    fused_attn<<<NB, NT>>>(hidden, enc, W, out);
}

// round 4
// speedup vs baseline: 1.0012x; 1.0012x over previous
#include <cuda_runtime.h>

#define H  2048
#define S  8192
#define NB 148
#define NT 1024
#define ROWS_PER_BLK 14     // 148 * 14 = 2072 >= 2048 (tail blocks predicated off)

// Scratch (no allocs allowed). g_u starts zero (static init); block 0 re-zeros
// it at the end of every invocation, so "g_u == 0 on entry" holds for the
// correctness run, the capture, and every graph replay.
__device__ float    g_u[H];
__device__ float    g_mb[NB];
__device__ float    g_zb[NB];
__device__ unsigned g_count = 0;   // barrier arrival counter (self-resetting)
__device__ unsigned g_gen   = 0;   // barrier generation (monotonic across replays)

// Software grid barrier. Safe: all NB=148 blocks resident (<=152 SMs, 1/SM).
// Sense via monotonic generation counter -> graph-replay safe.
__device__ __forceinline__ void grid_barrier() {
    __syncthreads();
    __threadfence();
    if (threadIdx.x == 0) {
        unsigned gen0 = *(volatile unsigned*)&g_gen;
        if (atomicAdd(&g_count, 1u) == NB - 1) {
            g_count = 0;
            __threadfence();
            atomicAdd(&g_gen, 1u);         // release
        } else {
            while (*(volatile unsigned*)&g_gen == gen0) { }
        }
        __threadfence();                   // acquire
    }
    __syncthreads();
}

__global__ __launch_bounds__(NT, 1)
void fused_attn(const float* __restrict__ hidden,
                const float* __restrict__ enc,
                const float* __restrict__ W,
                float* __restrict__ out) {
    const int b    = blockIdx.x;
    const int tid  = threadIdx.x;
    const int lane = tid & 31;
    const int wid  = tid >> 5;

    __shared__ float sU[H];        // staged u (8 KB)
    __shared__ float sE[56];       // this block's energies
    __shared__ float sM, sInvZ;

    // ---------------- Phase 1: u[j] = sum_i h[i] * W[i,j] ----------------
    // Fixed 14-row strip per block, COMPILE-TIME unrolled -> ~28 loads in
    // flight per thread. Threads cover columns tid and tid+1024 (coalesced).
    {
        const int i0 = b * ROWS_PER_BLK;
        float a0 = 0.0f, a1 = 0.0f;
#pragma unroll
        for (int ii = 0; ii < ROWS_PER_BLK; ++ii) {
            const int i = i0 + ii;
            if (i < H) {
                const float hv = __ldg(hidden + i);
                a0 = fmaf(hv, W[(size_t)i * H + tid],      a0);
                a1 = fmaf(hv, W[(size_t)i * H + tid + NT], a1);
            }
        }
        if (i0 < H) {
            atomicAdd(&g_u[tid],      a0);
            atomicAdd(&g_u[tid + NT], a1);
        }
    }

    grid_barrier();   // g_u complete

    // Stage u into shared memory (one pass; L2-hot after phase 1).
    sU[tid]      = g_u[tid];
    sU[tid + NT] = g_u[tid + NT];
    __syncthreads();

    // ---------------- Phase 2: energies + block-local (m, z) -------------
    // Block b handles rows s = b + k*NB (k = 0..nrows-1, nrows = 55 or 56).
    // One warp per row; enc streamed from DRAM (__ldcs), u from smem.
    const int nrows = (S - 1 - b) / NB + 1;
    const float4* uv = reinterpret_cast<const float4*>(sU);

    for (int k = wid; k < nrows; k += 32) {
        const int s = b + k * NB;
        const float4* row = reinterpret_cast<const float4*>(enc + (size_t)s * H);
        float acc = 0.0f;
#pragma unroll
        for (int t = 0; t < (H / 4) / 32; ++t) {   // 16 iterations
            float4 v = __ldcs(row + lane + t * 32);
            float4 u = uv[lane + t * 32];
            acc = fmaf(v.x, u.x, acc);
            acc = fmaf(v.y, u.y, acc);
            acc = fmaf(v.z, u.z, acc);
            acc = fmaf(v.w, u.w, acc);
        }
#pragma unroll
        for (int off = 16; off; off >>= 1)
            acc += __shfl_xor_sync(0xFFFFFFFFu, acc, off);
        if (lane == 0) sE[k] = acc;
    }
    __syncthreads();

    if (wid == 0) {
        const float v0 = (lane      < nrows) ? sE[lane]      : -1e30f;
        const float v1 = (lane + 32 < nrows) ? sE[lane + 32] : -1e30f;
        float m = fmaxf(v0, v1);
#pragma unroll
        for (int off = 16; off; off >>= 1)
            m = fmaxf(m, __shfl_xor_sync(0xFFFFFFFFu, m, off));
        float z = 0.0f;
        if (lane      < nrows) z += __expf(v0 - m);
        if (lane + 32 < nrows) z += __expf(v1 - m);
#pragma unroll
        for (int off = 16; off; off >>= 1)
            z += __shfl_xor_sync(0xFFFFFFFFu, z, off);
        if (lane == 0) { g_mb[b] = m; g_zb[b] = z; }
    }

    grid_barrier();   // all (m_b, z_b) visible

    // ---------------- Phase 3: global (M, 1/Z), redundant per block ------
    if (wid == 0) {
        float m = -1e30f;
        for (int i = lane; i < NB; i += 32) m = fmaxf(m, g_mb[i]);
#pragma unroll
        for (int off = 16; off; off >>= 1)
            m = fmaxf(m, __shfl_xor_sync(0xFFFFFFFFu, m, off));
        float z = 0.0f;
        for (int i = lane; i < NB; i += 32) z += g_zb[i] * __expf(g_mb[i] - m);
#pragma unroll
        for (int off = 16; off; off >>= 1)
            z += __shfl_xor_sync(0xFFFFFFFFu, z, off);
        if (lane == 0) { sM = m; sInvZ = 1.0f / z; }
    }
    __syncthreads();

    // ---------------- Phase 4: write softmax, restore g_u invariant ------
    if (tid < nrows)
        out[b + tid * NB] = __expf(sE[tid] - sM) * sInvZ;

    if (b == 0) {                  // all phase-2 g_u readers passed barrier 2
        g_u[tid]      = 0.0f;
        g_u[tid + NT] = 0.0f;
    }
}

// ---------------------------------------------------------------------------
// Launch. Inputs: hidden[2048], encoder_outputs[8192*2048], W[2048*2048],
// b[2048] (zero + softmax-invariant -> ignored). Output: 8192 floats.
// ---------------------------------------------------------------------------
extern "C" void kernel_launch(void* const* d_in, const int* in_sizes, int n_in,
                              void* d_out, int out_size) {
    const float* hidden = (const float*)d_in[0];
    const float* enc    = (const float*)d_in[1];
    const float* W      = (const float*)d_in[2];
    float* out          = (float*)d_out;

    fused_attn<<<NB, NT>>>(hidden, enc, W, out);
}